// round 14
// baseline (speedup 1.0000x reference)
#include <cuda_runtime.h>
#include <cuda_fp16.h>
#include <cstdint>

// One CTA per batch row b (B=4096), 256 threads, 8 samples/thread (n=2048).
// All samples of a row land in an 8^3 voxel window (|bound_psf|*SCL < 2.52,
// margin 0.02). Per-row setup computed by WARP 0 ONLY (CTA-uniform work),
// broadcast via SMEM. Two-phase staging:
//   phase 1: coalesced copy of raw 8^3 fp32 window -> sv32[512] (zero OOB)
//   phase 2: build fp16 y-pair layout:
//     svh[(z*7+y)*7+x] = { half2(v[x,y], v[x,y+1]), half2(v[x+1,y], v[x+1,y+1]) }
// Trilinear = 2x LDS.64 + HSUB2/HFMA2 x-lerp + fp32 y/z lerp.
// launch_bounds(256,8): 32 regs -> 8 CTAs/SM.

#define SPAN 8
#define NTHREADS 256
#define SPT 8
#define SCL (256.0f / 255.0f)
#define NEG_HALF_LOG2E (-0.72134752044448170368f)

__device__ __forceinline__ float tanh_fast(float x) {
    float y;
    asm("tanh.approx.f32 %0, %1;" : "=f"(y) : "f"(x));
    return y;
}

__device__ __forceinline__ unsigned int pack_h2(float a, float b) {
    const __half2 h = __floats2half2_rn(a, b);
    return *(const unsigned int*)&h;
}

__global__ __launch_bounds__(NTHREADS, 8)
void select_profile_kernel(
    const float* __restrict__ vol,       // [256,256,256]
    const float* __restrict__ sg,        // [B,3]
    const float* __restrict__ ax,        // [B,1,6]
    const float* __restrict__ bound,     // [B,2,3]
    const float* __restrict__ icov,      // [B,3,3]
    const float* __restrict__ xyz,       // [B,n,3]
    float* __restrict__ out,             // [B]
    int n)
{
    __shared__ float sv32[SPAN * SPAN * SPAN];         // 2 KB raw fp32 window
    __shared__ uint2 svh[SPAN * 7 * 7];                // 3.1 KB fp16 y-pairs
    __shared__ float prm[12];
    __shared__ int   wlo[3];
    __shared__ float rnum[NTHREADS / 32];
    __shared__ float rden[NTHREADS / 32];

    const int b   = blockIdx.x;
    const int tid = threadIdx.x;

    // ---- per-row parameters: warp 0 only (uniform work), SMEM broadcast ----
    if (tid < 32) {
        const float vx = __ldg(&ax[b * 6 + 0]), vy = __ldg(&ax[b * 6 + 1]), vz = __ldg(&ax[b * 6 + 2]);
        const float Tx = __ldg(&ax[b * 6 + 3]), Ty = __ldg(&ax[b * 6 + 4]), Tz = __ldg(&ax[b * 6 + 5]);

        const float th  = sqrtf(vx * vx + vy * vy + vz * vz + 1e-12f);
        const float itn = 1.0f / th;
        const float kx = vx * itn, ky = vy * itn, kz = vz * itn;
        float s, cth;
        __sincosf(th, &s, &cth);
        const float c = 1.0f - cth;

        const float R00 = 1.0f + c * (kx * kx - 1.0f);
        const float R01 = -s * kz + c * kx * ky;
        const float R02 =  s * ky + c * kx * kz;
        const float R10 =  s * kz + c * kx * ky;
        const float R11 = 1.0f + c * (ky * ky - 1.0f);
        const float R12 = -s * kx + c * ky * kz;
        const float R20 = -s * ky + c * kx * kz;
        const float R21 =  s * kx + c * ky * kz;
        const float R22 = 1.0f + c * (kz * kz - 1.0f);

        const float px = __ldg(&sg[b * 3 + 0]) + Tx;
        const float py = __ldg(&sg[b * 3 + 1]) + Ty;
        const float pz = __ldg(&sg[b * 3 + 2]) + Tz;

        const float cxw = R00 * px + R01 * py + R02 * pz;
        const float cyw = R10 * px + R11 * py + R12 * pz;
        const float czw = R20 * px + R21 * py + R22 * pz;

        const float hx = (__ldg(&bound[b * 6 + 3]) - __ldg(&bound[b * 6 + 0])) * 0.5f;
        const float hy = (__ldg(&bound[b * 6 + 4]) - __ldg(&bound[b * 6 + 1])) * 0.5f;
        const float hz = (__ldg(&bound[b * 6 + 5]) - __ldg(&bound[b * 6 + 2])) * 0.5f;

        const float cx2 = cxw * SCL - 0.5f;
        const float cy2 = cyw * SCL - 0.5f;
        const float cz2 = czw * SCL - 0.5f;

        const int lox = (int)floorf(cx2 - hx * SCL - 0.02f);
        const int loy = (int)floorf(cy2 - hy * SCL - 0.02f);
        const int loz = (int)floorf(cz2 - hz * SCL - 0.02f);

        const float* M = icov + (size_t)b * 9;
        if (tid == 0) {
            prm[0] = cx2 - (float)lox;   // window-local center
            prm[1] = cy2 - (float)loy;
            prm[2] = cz2 - (float)loz;
            prm[3] = hx * SCL;
            prm[4] = hy * SCL;
            prm[5] = hz * SCL;
            prm[6]  = __ldg(M + 0) * NEG_HALF_LOG2E * hx * hx;
            prm[7]  = __ldg(M + 4) * NEG_HALF_LOG2E * hy * hy;
            prm[8]  = __ldg(M + 8) * NEG_HALF_LOG2E * hz * hz;
            prm[9]  = (__ldg(M + 1) + __ldg(M + 3)) * NEG_HALF_LOG2E * hx * hy;
            prm[10] = (__ldg(M + 2) + __ldg(M + 6)) * NEG_HALF_LOG2E * hx * hz;
            prm[11] = (__ldg(M + 5) + __ldg(M + 7)) * NEG_HALF_LOG2E * hy * hz;
            wlo[0] = lox; wlo[1] = loy; wlo[2] = loz;
        }
    }
    __syncthreads();

    const int lox = wlo[0], loy = wlo[1], loz = wlo[2];

    // ---- phase 1: coalesced raw window copy (zero OOB) ----
    #pragma unroll
    for (int idx = tid; idx < SPAN * SPAN * SPAN; idx += NTHREADS) {
        const int xg = lox + (idx & 7);
        const int yg = loy + ((idx >> 3) & 7);
        const int zg = loz + (idx >> 6);
        float v = 0.0f;
        if ((unsigned)xg < 256u && (unsigned)yg < 256u && (unsigned)zg < 256u)
            v = __ldg(&vol[((size_t)zg * 256 + yg) * 256 + xg]);
        sv32[idx] = v;
    }
    __syncthreads();

    // ---- phase 2: build fp16 y-pair layout from SMEM ----
    #pragma unroll
    for (int idx = tid; idx < SPAN * 7 * 7; idx += NTHREADS) {
        const int x = idx % 7;
        const int zy = idx / 7;
        const int y = zy % 7;
        const int z = zy / 7;
        const int s0 = (z * SPAN + y) * SPAN + x;
        uint2 packed;
        packed.x = pack_h2(sv32[s0],     sv32[s0 + SPAN]);     // (v[x,y],   v[x,y+1])
        packed.y = pack_h2(sv32[s0 + 1], sv32[s0 + SPAN + 1]); // (v[x+1,y], v[x+1,y+1])
        svh[idx] = packed;
    }
    __syncthreads();

    const float cxl = prm[0], cyl = prm[1], czl = prm[2];
    const float hxS = prm[3], hyS = prm[4], hzS = prm[5];
    const float M00 = prm[6], M11 = prm[7], M22 = prm[8];
    const float S01 = prm[9], S02 = prm[10], S12 = prm[11];

    float num = 0.0f, den = 0.0f;

    for (int i0 = tid * SPT; i0 < n; i0 += NTHREADS * SPT) {
        const float4* p4 = (const float4*)(xyz + ((size_t)b * n + i0) * 3);

        #pragma unroll
        for (int g = 0; g < SPT / 4; g++) {
            // 4 samples = 12 floats = 3 aligned float4
            const float4 r0 = __ldcs(p4 + g * 3 + 0);
            const float4 r1 = __ldcs(p4 + g * 3 + 1);
            const float4 r2 = __ldcs(p4 + g * 3 + 2);
            const float sx[4] = { r0.x, r0.w, r1.z, r2.y };
            const float sy[4] = { r0.y, r1.x, r1.w, r2.z };
            const float sz[4] = { r0.z, r1.y, r2.x, r2.w };

            #pragma unroll
            for (int j = 0; j < 4; j++) {
                // u = 2*sigmoid(t) - 1 = tanh(t/2)
                const float ux = tanh_fast(0.5f * sx[j]);
                const float uy = tanh_fast(0.5f * sy[j]);
                const float uz = tanh_fast(0.5f * sz[j]);

                const float lxf = fmaf(ux, hxS, cxl);
                const float lyf = fmaf(uy, hyS, cyl);
                const float lzf = fmaf(uz, hzS, czl);

                const float x0f = floorf(lxf);
                const float y0f = floorf(lyf);
                const float z0f = floorf(lzf);
                const float fx = lxf - x0f;
                const float fy = lyf - y0f;
                const float fz = lzf - z0f;

                const int bi = (int)fmaf(fmaf(z0f, 7.0f, y0f), 7.0f, x0f);

                // two LDS.64, issued back-to-back
                const uint2 t0 = svh[bi];         // z0  : (v000,v010),(v001,v011)
                const uint2 t1 = svh[bi + 49];    // z0+1: (v100,v110),(v101,v111)

                // x-lerp of both y-rows in one HSUB2+HFMA2 per z-plane
                const __half2 fx2 = __float2half2_rn(fx);
                const __half2 a0 = *(const __half2*)&t0.x;
                const __half2 b0 = *(const __half2*)&t0.y;
                const __half2 a1 = *(const __half2*)&t1.x;
                const __half2 b1 = *(const __half2*)&t1.y;
                const __half2 c0h = __hfma2(fx2, __hsub2(b0, a0), a0); // (c00,c01)
                const __half2 c1h = __hfma2(fx2, __hsub2(b1, a1), a1); // (c10,c11)

                const float2 p0 = __half22float2(c0h);
                const float2 p1 = __half22float2(c1h);

                const float c0 = fmaf(fy, p0.y - p0.x, p0.x);
                const float c1 = fmaf(fy, p1.y - p1.x, p1.x);
                const float pv = fmaf(fz, c1 - c0, c0);

                const float t1q = fmaf(M00, ux, fmaf(S01, uy, S02 * uz));
                const float t2q = fmaf(M11, uy, S12 * uz);
                const float qf  = fmaf(ux, t1q, fmaf(uy, t2q, uz * (M22 * uz)));
                const float w   = exp2f(qf);

                num = fmaf(pv, w, num);
                den += w;
            }
        }
    }

    // ---- reduction ----
    #pragma unroll
    for (int o = 16; o > 0; o >>= 1) {
        num += __shfl_xor_sync(0xFFFFFFFFu, num, o);
        den += __shfl_xor_sync(0xFFFFFFFFu, den, o);
    }
    if ((tid & 31) == 0) {
        rnum[tid >> 5] = num;
        rden[tid >> 5] = den;
    }
    __syncthreads();
    if (tid == 0) {
        float N = 0.0f, Dn = 0.0f;
        #pragma unroll
        for (int i = 0; i < NTHREADS / 32; i++) { N += rnum[i]; Dn += rden[i]; }
        out[b] = N / Dn;
    }
}

extern "C" void kernel_launch(void* const* d_in, const int* in_sizes, int n_in,
                              void* d_out, int out_size) {
    const float* vol   = (const float*)d_in[0];  // x [1,1,256,256,256]
    const float* sg    = (const float*)d_in[1];  // sampleGrid [B,3]
    const float* ax    = (const float*)d_in[2];  // ax [B,1,6]
    const float* bound = (const float*)d_in[3];  // bound [B,2,3]
    const float* icov  = (const float*)d_in[4];  // InvCovScaled [B,3,3]
    // d_in[5] = psf_sigma (unused by reference)
    const float* xyz   = (const float*)d_in[6];  // xyz_psf [B,n,3]
    float* out = (float*)d_out;

    const int B = in_sizes[1] / 3;
    const int n = in_sizes[6] / (B * 3);

    select_profile_kernel<<<B, NTHREADS>>>(vol, sg, ax, bound, icov, xyz, out, n);
}

// round 15
// speedup vs baseline: 1.0425x; 1.0425x over previous
#include <cuda_runtime.h>
#include <cuda_fp16.h>
#include <cstdint>

// One CTA per batch row b (B=4096), 256 threads, 8 samples/thread (n=2048).
// All samples of a row land in an 8^3 voxel window (|bound_psf|*SCL < 2.52,
// margin 0.02). Per-thread redundant setup (R13 structure). Two-phase staging:
//   phase 1: coalesced copy of raw 8^3 fp32 window -> sv32[512] (zero OOB)
//   phase 2: fp16 y-pair layout:
//     svh[(z*7+y)*7+x] = { half2(v[x,y], v[x,y+1]), half2(v[x+1,y], v[x+1,y+1]) }
// Trilinear = 2x LDS.64 + HSUB2/HFMA2 x-lerp + fp32 y/z lerp.
// MUFU halved: tanh.approx.f16x2 (2 samples/op) + ex2.approx.f16x2 (2 weights/op).
// launch_bounds(256,8): target 32 regs -> 8 CTAs/SM.

#define SPAN 8
#define NTHREADS 256
#define SPT 8
#define SCL (256.0f / 255.0f)
#define NEG_HALF_LOG2E (-0.72134752044448170368f)

__device__ __forceinline__ unsigned int pack_h2(float a, float b) {
    const __half2 h = __floats2half2_rn(a, b);
    return *(const unsigned int*)&h;
}

__device__ __forceinline__ __half2 h2_tanh(__half2 x) {
    unsigned int xi = *(const unsigned int*)&x, yo;
    asm("tanh.approx.f16x2 %0, %1;" : "=r"(yo) : "r"(xi));
    return *(__half2*)&yo;
}

__device__ __forceinline__ __half2 h2_ex2(__half2 x) {
    unsigned int xi = *(const unsigned int*)&x, yo;
    asm("ex2.approx.f16x2 %0, %1;" : "=r"(yo) : "r"(xi));
    return *(__half2*)&yo;
}

__global__ __launch_bounds__(NTHREADS, 8)
void select_profile_kernel(
    const float* __restrict__ vol,       // [256,256,256]
    const float* __restrict__ sg,        // [B,3]
    const float* __restrict__ ax,        // [B,1,6]
    const float* __restrict__ bound,     // [B,2,3]
    const float* __restrict__ icov,      // [B,3,3]
    const float* __restrict__ xyz,       // [B,n,3]
    float* __restrict__ out,             // [B]
    int n)
{
    __shared__ float sv32[SPAN * SPAN * SPAN];         // 2 KB raw fp32 window
    __shared__ uint2 svh[SPAN * 7 * 7];                // 3.1 KB fp16 y-pairs
    __shared__ float rnum[NTHREADS / 32];
    __shared__ float rden[NTHREADS / 32];

    const int b   = blockIdx.x;
    const int tid = threadIdx.x;

    // ---- per-row parameters (redundant per thread; broadcast L1 hits) ----
    const float vx = __ldg(&ax[b * 6 + 0]), vy = __ldg(&ax[b * 6 + 1]), vz = __ldg(&ax[b * 6 + 2]);
    const float Tx = __ldg(&ax[b * 6 + 3]), Ty = __ldg(&ax[b * 6 + 4]), Tz = __ldg(&ax[b * 6 + 5]);

    const float th  = sqrtf(vx * vx + vy * vy + vz * vz + 1e-12f);
    const float itn = 1.0f / th;
    const float kx = vx * itn, ky = vy * itn, kz = vz * itn;
    float s, cth;
    __sincosf(th, &s, &cth);
    const float c = 1.0f - cth;

    const float R00 = 1.0f + c * (kx * kx - 1.0f);
    const float R01 = -s * kz + c * kx * ky;
    const float R02 =  s * ky + c * kx * kz;
    const float R10 =  s * kz + c * kx * ky;
    const float R11 = 1.0f + c * (ky * ky - 1.0f);
    const float R12 = -s * kx + c * ky * kz;
    const float R20 = -s * ky + c * kx * kz;
    const float R21 =  s * kx + c * ky * kz;
    const float R22 = 1.0f + c * (kz * kz - 1.0f);

    const float px = __ldg(&sg[b * 3 + 0]) + Tx;
    const float py = __ldg(&sg[b * 3 + 1]) + Ty;
    const float pz = __ldg(&sg[b * 3 + 2]) + Tz;

    const float cxw = R00 * px + R01 * py + R02 * pz;
    const float cyw = R10 * px + R11 * py + R12 * pz;
    const float czw = R20 * px + R21 * py + R22 * pz;

    const float hx = (__ldg(&bound[b * 6 + 3]) - __ldg(&bound[b * 6 + 0])) * 0.5f;
    const float hy = (__ldg(&bound[b * 6 + 4]) - __ldg(&bound[b * 6 + 1])) * 0.5f;
    const float hz = (__ldg(&bound[b * 6 + 5]) - __ldg(&bound[b * 6 + 2])) * 0.5f;

    const float cx2 = cxw * SCL - 0.5f;
    const float cy2 = cyw * SCL - 0.5f;
    const float cz2 = czw * SCL - 0.5f;

    const int lox = (int)floorf(cx2 - hx * SCL - 0.02f);
    const int loy = (int)floorf(cy2 - hy * SCL - 0.02f);
    const int loz = (int)floorf(cz2 - hz * SCL - 0.02f);

    const float cxl = cx2 - (float)lox;   // window-local center
    const float cyl = cy2 - (float)loy;
    const float czl = cz2 - (float)loz;

    const float hxS = hx * SCL, hyS = hy * SCL, hzS = hz * SCL;

    // quadratic form in u = tanh(0.5*t) with h folded, pre-scaled by -0.5*log2(e)
    const float* M = icov + (size_t)b * 9;
    const float M00 = __ldg(M + 0) * NEG_HALF_LOG2E * hx * hx;
    const float M11 = __ldg(M + 4) * NEG_HALF_LOG2E * hy * hy;
    const float M22 = __ldg(M + 8) * NEG_HALF_LOG2E * hz * hz;
    const float S01 = (__ldg(M + 1) + __ldg(M + 3)) * NEG_HALF_LOG2E * hx * hy;
    const float S02 = (__ldg(M + 2) + __ldg(M + 6)) * NEG_HALF_LOG2E * hx * hz;
    const float S12 = (__ldg(M + 5) + __ldg(M + 7)) * NEG_HALF_LOG2E * hy * hz;

    // ---- phase 1: coalesced raw window copy (zero OOB) ----
    #pragma unroll
    for (int idx = tid; idx < SPAN * SPAN * SPAN; idx += NTHREADS) {
        const int xg = lox + (idx & 7);
        const int yg = loy + ((idx >> 3) & 7);
        const int zg = loz + (idx >> 6);
        float v = 0.0f;
        if ((unsigned)xg < 256u && (unsigned)yg < 256u && (unsigned)zg < 256u)
            v = __ldg(&vol[((size_t)zg * 256 + yg) * 256 + xg]);
        sv32[idx] = v;
    }
    __syncthreads();

    // ---- phase 2: build fp16 y-pair layout from SMEM ----
    #pragma unroll
    for (int idx = tid; idx < SPAN * 7 * 7; idx += NTHREADS) {
        const int x = idx % 7;
        const int zy = idx / 7;
        const int y = zy % 7;
        const int z = zy / 7;
        const int s0 = (z * SPAN + y) * SPAN + x;
        uint2 packed;
        packed.x = pack_h2(sv32[s0],     sv32[s0 + SPAN]);     // (v[x,y],   v[x,y+1])
        packed.y = pack_h2(sv32[s0 + 1], sv32[s0 + SPAN + 1]); // (v[x+1,y], v[x+1,y+1])
        svh[idx] = packed;
    }
    __syncthreads();

    float num = 0.0f, den = 0.0f;

    for (int i0 = tid * SPT; i0 < n; i0 += NTHREADS * SPT) {
        const float4* p4 = (const float4*)(xyz + ((size_t)b * n + i0) * 3);

        #pragma unroll
        for (int g = 0; g < SPT / 4; g++) {
            // 4 samples = 12 floats = 3 aligned float4
            const float4 r0 = __ldcs(p4 + g * 3 + 0);
            const float4 r1 = __ldcs(p4 + g * 3 + 1);
            const float4 r2 = __ldcs(p4 + g * 3 + 2);
            const float sx[4] = { r0.x, r0.w, r1.z, r2.y };
            const float sy[4] = { r0.y, r1.x, r1.w, r2.z };
            const float sz[4] = { r0.z, r1.y, r2.x, r2.w };

            #pragma unroll
            for (int p = 0; p < 2; p++) {
                const int a0i = 2 * p, a1i = 2 * p + 1;

                // u = tanh(t/2) for BOTH samples of the pair in one MUFU op each
                const float2 uxf = __half22float2(
                    h2_tanh(__floats2half2_rn(0.5f * sx[a0i], 0.5f * sx[a1i])));
                const float2 uyf = __half22float2(
                    h2_tanh(__floats2half2_rn(0.5f * sy[a0i], 0.5f * sy[a1i])));
                const float2 uzf = __half22float2(
                    h2_tanh(__floats2half2_rn(0.5f * sz[a0i], 0.5f * sz[a1i])));

                float pv[2], qq[2];
                #pragma unroll
                for (int k = 0; k < 2; k++) {
                    const float ux = k ? uxf.y : uxf.x;
                    const float uy = k ? uyf.y : uyf.x;
                    const float uz = k ? uzf.y : uzf.x;

                    const float lxf = fmaf(ux, hxS, cxl);
                    const float lyf = fmaf(uy, hyS, cyl);
                    const float lzf = fmaf(uz, hzS, czl);

                    const float x0f = floorf(lxf);
                    const float y0f = floorf(lyf);
                    const float z0f = floorf(lzf);
                    const float fx = lxf - x0f;
                    const float fy = lyf - y0f;
                    const float fz = lzf - z0f;

                    const int bi = (int)fmaf(fmaf(z0f, 7.0f, y0f), 7.0f, x0f);

                    // two LDS.64, issued back-to-back
                    const uint2 t0 = svh[bi];       // z0  : (v000,v010),(v001,v011)
                    const uint2 t1 = svh[bi + 49];  // z0+1: (v100,v110),(v101,v111)

                    // x-lerp of both y-rows in one HSUB2+HFMA2 per z-plane
                    const __half2 fx2 = __float2half2_rn(fx);
                    const __half2 a0 = *(const __half2*)&t0.x;
                    const __half2 b0 = *(const __half2*)&t0.y;
                    const __half2 a1 = *(const __half2*)&t1.x;
                    const __half2 b1 = *(const __half2*)&t1.y;
                    const __half2 c0h = __hfma2(fx2, __hsub2(b0, a0), a0); // (c00,c01)
                    const __half2 c1h = __hfma2(fx2, __hsub2(b1, a1), a1); // (c10,c11)

                    const float2 p0 = __half22float2(c0h);
                    const float2 p1 = __half22float2(c1h);

                    const float c0 = fmaf(fy, p0.y - p0.x, p0.x);
                    const float c1 = fmaf(fy, p1.y - p1.x, p1.x);
                    pv[k] = fmaf(fz, c1 - c0, c0);

                    const float t1q = fmaf(M00, ux, fmaf(S01, uy, S02 * uz));
                    const float t2q = fmaf(M11, uy, S12 * uz);
                    qq[k] = fmaf(ux, t1q, fmaf(uy, t2q, uz * (M22 * uz)));
                }

                // both weights in one MUFU op: w = 2^q (q <= 0)
                const float2 wf = __half22float2(
                    h2_ex2(__floats2half2_rn(qq[0], qq[1])));

                num = fmaf(pv[0], wf.x, num);
                num = fmaf(pv[1], wf.y, num);
                den += wf.x + wf.y;
            }
        }
    }

    // ---- reduction ----
    #pragma unroll
    for (int o = 16; o > 0; o >>= 1) {
        num += __shfl_xor_sync(0xFFFFFFFFu, num, o);
        den += __shfl_xor_sync(0xFFFFFFFFu, den, o);
    }
    if ((tid & 31) == 0) {
        rnum[tid >> 5] = num;
        rden[tid >> 5] = den;
    }
    __syncthreads();
    if (tid == 0) {
        float N = 0.0f, Dn = 0.0f;
        #pragma unroll
        for (int i = 0; i < NTHREADS / 32; i++) { N += rnum[i]; Dn += rden[i]; }
        out[b] = N / Dn;
    }
}

extern "C" void kernel_launch(void* const* d_in, const int* in_sizes, int n_in,
                              void* d_out, int out_size) {
    const float* vol   = (const float*)d_in[0];  // x [1,1,256,256,256]
    const float* sg    = (const float*)d_in[1];  // sampleGrid [B,3]
    const float* ax    = (const float*)d_in[2];  // ax [B,1,6]
    const float* bound = (const float*)d_in[3];  // bound [B,2,3]
    const float* icov  = (const float*)d_in[4];  // InvCovScaled [B,3,3]
    // d_in[5] = psf_sigma (unused by reference)
    const float* xyz   = (const float*)d_in[6];  // xyz_psf [B,n,3]
    float* out = (float*)d_out;

    const int B = in_sizes[1] / 3;
    const int n = in_sizes[6] / (B * 3);

    select_profile_kernel<<<B, NTHREADS>>>(vol, sg, ax, bound, icov, xyz, out, n);
}